// round 4
// baseline (speedup 1.0000x reference)
#include <cuda_runtime.h>
#include <math.h>

#define BATCH 2048
#define NP    32
#define DD    6
#define NOBS  17
#define NIN   23        // OBS + D
#define HID   256
#define NSTEPS 10
#define LRATE 0.1f
#define CLIP_LIM 1.0f
// np.float32(np.log(33.0))
#define LOG_NP1 3.49650756f

// W2 transposed scratch (allocation-free: __device__ global)
__device__ __align__(256) float g_W2T[HID * HID];

// ---------------------------------------------------------------------------
// packed f32x2 helpers (Blackwell FFMA2 via PTX)
// ---------------------------------------------------------------------------
__device__ __forceinline__ unsigned long long splat2(float a) {
    unsigned long long r;
    asm("mov.b64 %0, {%1, %1};" : "=l"(r) : "f"(a));
    return r;
}
__device__ __forceinline__ void ffma2(unsigned long long& d,
                                      unsigned long long a,
                                      unsigned long long b) {
    asm("fma.rn.f32x2 %0, %1, %2, %0;" : "+l"(d) : "l"(a), "l"(b));
}
__device__ __forceinline__ float2 unpack2(unsigned long long v) {
    float2 f;
    asm("mov.b64 {%0, %1}, %2;" : "=f"(f.x), "=f"(f.y) : "l"(v));
    return f;
}

// ---------------------------------------------------------------------------
// One-time transpose of W2 (coalesced weights for the backward matmul).
// ---------------------------------------------------------------------------
__global__ void transposeW2_kernel(const float* __restrict__ W2) {
    __shared__ float tile[32][33];
    int bx = blockIdx.x, by = blockIdx.y;
    int x = bx * 32 + threadIdx.x;
#pragma unroll
    for (int i = 0; i < 32; i += 8) {
        int y = by * 32 + threadIdx.y + i;
        tile[threadIdx.y + i][threadIdx.x] = W2[y * HID + x];
    }
    __syncthreads();
    int xo = by * 32 + threadIdx.x;
#pragma unroll
    for (int i = 0; i < 32; i += 8) {
        int yo = bx * 32 + threadIdx.y + i;
        g_W2T[yo * HID + xo] = tile[threadIdx.x][threadIdx.y + i];
    }
}

// ---------------------------------------------------------------------------
// Swizzled transposed activation index: logical arr[c][r] (c = feature,
// r = particle row 0..31). Quad-granular XOR swizzle keeps quads intact
// (aligned float4 ops) while spreading bank groups across c.
// ---------------------------------------------------------------------------
__device__ __forceinline__ int atidx(int c, int r) {
    return c * 32 + (r ^ ((c & 7) << 2));
}

struct __align__(16) Smem {
    float inT[NIN * 32 + 32];   // swizzled transposed concat(obs, X), 23x32
    float hT[HID * 32];         // swizzled transposed relu(z1); later dz1
    float dT[HID * 32];         // swizzled transposed dz2
    float b1[HID];
    float b2[HID];
    float W3[HID];
    float X[2][NP * DD];        // ping-pong particle positions (row-major)
    float s[NP * DD];           // scores
    float dsq[NP * NP];
    float sortbuf[512];         // upper-triangle (496) + inf pad
    float logp[NP];
    float gamma;
};

extern __shared__ float smem_raw[];

// ---------------------------------------------------------------------------
// Core matmul: out[32 rows x 256 cols] = A(32 x K) @ B(K x 256).
// A given transposed+swizzled (AT[k][r]); B row-major in gmem, coalesced.
// Warp tile: 8 rows x 128 cols; thread: 8 rows x 4 cols, acc packed over
// row pairs. acc[p*4+i]: rows (rw+2p, rw+2p+1), col c0+i.
// ---------------------------------------------------------------------------
template <int K>
__device__ __forceinline__ void mm_core(const float* __restrict__ AT,
                                        const float* __restrict__ Bg,
                                        int rw, int c0,
                                        unsigned long long acc[16]) {
#pragma unroll
    for (int i = 0; i < 16; i++) acc[i] = 0ull;
#pragma unroll 8
    for (int k = 0; k < K; k++) {
        const int m = (k & 7) << 2;
        const ulonglong2 A0 = *reinterpret_cast<const ulonglong2*>(
            AT + k * 32 + (rw ^ m));            // rows rw..rw+3 (pairs)
        const ulonglong2 A1 = *reinterpret_cast<const ulonglong2*>(
            AT + k * 32 + ((rw + 4) ^ m));      // rows rw+4..rw+7
        const float4 bw = *reinterpret_cast<const float4*>(Bg + k * HID + c0);
        const unsigned long long s0 = splat2(bw.x);
        const unsigned long long s1 = splat2(bw.y);
        const unsigned long long s2 = splat2(bw.z);
        const unsigned long long s3 = splat2(bw.w);
        ffma2(acc[0],  A0.x, s0); ffma2(acc[1],  A0.x, s1);
        ffma2(acc[2],  A0.x, s2); ffma2(acc[3],  A0.x, s3);
        ffma2(acc[4],  A0.y, s0); ffma2(acc[5],  A0.y, s1);
        ffma2(acc[6],  A0.y, s2); ffma2(acc[7],  A0.y, s3);
        ffma2(acc[8],  A1.x, s0); ffma2(acc[9],  A1.x, s1);
        ffma2(acc[10], A1.x, s2); ffma2(acc[11], A1.x, s3);
        ffma2(acc[12], A1.y, s0); ffma2(acc[13], A1.y, s1);
        ffma2(acc[14], A1.y, s2); ffma2(acc[15], A1.y, s3);
    }
}

__global__ void __launch_bounds__(256, 2) svgd_kernel(
    const float* __restrict__ g_obs, const float* __restrict__ g_a,
    const float* __restrict__ g_W1, const float* __restrict__ g_b1,
    const float* __restrict__ g_W2, const float* __restrict__ g_b2,
    const float* __restrict__ g_W3, float* __restrict__ g_out)
{
    Smem* sm = reinterpret_cast<Smem*>(smem_raw);
    const int tid = threadIdx.x;
    const int b = blockIdx.x;
    const int warp = tid >> 5;
    const int lane = tid & 31;
    // matmul tile coords: warp -> (row group, col half); lane -> 4 cols
    const int rw = (warp >> 1) * 8;
    const int c0 = (warp & 1) * 128 + lane * 4;

    // ---- one-time loads --------------------------------------------------
    sm->b1[tid] = g_b1[tid];
    sm->b2[tid] = g_b2[tid];
    sm->W3[tid] = g_W3[tid];
    for (int i = tid; i < NP * DD; i += 256) sm->X[0][i] = g_a[b * NP * DD + i];
    // obs part of inT (k = 0..16), swizzled transposed; built once
    for (int idx = tid; idx < NOBS * 32; idx += 256) {
        const int k = idx >> 5, r = idx & 31;
        sm->inT[atidx(k, r)] = g_obs[b * NP * NOBS + r * NOBS + k];
    }
    if (tid < NP) sm->logp[tid] = 0.0f;
    __syncthreads();

    int cur = 0;
    for (int step = 0; step < NSTEPS; step++) {
        const float* X = sm->X[cur];

        // ---- refresh X part of inT (k = 17..22) -------------------------
        if (tid < DD * 32) {
            const int d = tid >> 5, r = tid & 31;
            sm->inT[atidx(NOBS + d, r)] = X[r * DD + d];
        }
        __syncthreads();

        // ---- z1 = relu(in @ W1 + b1) -> hT (swizzled transposed) --------
        {
            unsigned long long acc[16];
            mm_core<NIN>(sm->inT, g_W1, rw, c0, acc);
#pragma unroll
            for (int i = 0; i < 4; i++) {
                const int c = c0 + i;
                const float bb = sm->b1[c];
                const int sw = (c & 7) << 2;
#pragma unroll
                for (int q = 0; q < 2; q++) {
                    float2 lo = unpack2(acc[(2 * q) * 4 + i]);
                    float2 hi = unpack2(acc[(2 * q + 1) * 4 + i]);
                    float4 v;
                    v.x = fmaxf(lo.x + bb, 0.0f);
                    v.y = fmaxf(lo.y + bb, 0.0f);
                    v.z = fmaxf(hi.x + bb, 0.0f);
                    v.w = fmaxf(hi.y + bb, 0.0f);
                    *reinterpret_cast<float4*>(
                        &sm->hT[c * 32 + ((rw + 4 * q) ^ sw)]) = v;
                }
            }
        }
        __syncthreads();

        // ---- z2 = h1 @ W2 + b2 ; dz2 = (z2>0)*W3 -> dT ------------------
        {
            unsigned long long acc[16];
            mm_core<HID>(sm->hT, g_W2, rw, c0, acc);
#pragma unroll
            for (int i = 0; i < 4; i++) {
                const int c = c0 + i;
                const float bb = sm->b2[c];
                const float w3 = sm->W3[c];
                const int sw = (c & 7) << 2;
#pragma unroll
                for (int q = 0; q < 2; q++) {
                    float2 lo = unpack2(acc[(2 * q) * 4 + i]);
                    float2 hi = unpack2(acc[(2 * q + 1) * 4 + i]);
                    float4 v;
                    v.x = (lo.x + bb > 0.0f) ? w3 : 0.0f;
                    v.y = (lo.y + bb > 0.0f) ? w3 : 0.0f;
                    v.z = (hi.x + bb > 0.0f) ? w3 : 0.0f;
                    v.w = (hi.y + bb > 0.0f) ? w3 : 0.0f;
                    *reinterpret_cast<float4*>(
                        &sm->dT[c * 32 + ((rw + 4 * q) ^ sw)]) = v;
                }
            }
        }
        __syncthreads();

        // ---- dz1 = (h1>0) * (dz2 @ W2^T) -> overwrite hT ----------------
        {
            unsigned long long acc[16];
            mm_core<HID>(sm->dT, g_W2T, rw, c0, acc);
#pragma unroll
            for (int i = 0; i < 4; i++) {
                const int c = c0 + i;
                const int sw = (c & 7) << 2;
#pragma unroll
                for (int q = 0; q < 2; q++) {
                    const int idx = c * 32 + ((rw + 4 * q) ^ sw);
                    float4 mk = *reinterpret_cast<const float4*>(&sm->hT[idx]);
                    float2 lo = unpack2(acc[(2 * q) * 4 + i]);
                    float2 hi = unpack2(acc[(2 * q + 1) * 4 + i]);
                    float4 v;
                    v.x = (mk.x > 0.0f) ? lo.x : 0.0f;
                    v.y = (mk.y > 0.0f) ? lo.y : 0.0f;
                    v.z = (mk.z > 0.0f) ? hi.x : 0.0f;
                    v.w = (mk.w > 0.0f) ? hi.y : 0.0f;
                    *reinterpret_cast<float4*>(&sm->hT[idx]) = v;
                }
            }
        }
        __syncthreads();

        // ---- score = dz1 @ W1[17:23,:]^T  (warp per 4 rows) -------------
        {
            const int swl = (lane & 7) << 2;
            for (int r = warp * 4; r < warp * 4 + 4; r++) {
                float dz[8];
#pragma unroll
                for (int i = 0; i < 8; i++)
                    dz[i] = sm->hT[(lane + 32 * i) * 32 + (r ^ swl)];
                float p[DD];
#pragma unroll
                for (int d = 0; d < DD; d++) {
                    float t = 0.0f;
#pragma unroll
                    for (int i = 0; i < 8; i++)
                        t = fmaf(dz[i], g_W1[(NOBS + d) * HID + lane + 32 * i], t);
#pragma unroll
                    for (int off = 16; off > 0; off >>= 1)
                        t += __shfl_xor_sync(0xFFFFFFFFu, t, off);
                    p[d] = t;
                }
                if (lane == 0) {
#pragma unroll
                    for (int d = 0; d < DD; d++) sm->s[r * DD + d] = p[d];
                }
            }
        }
        __syncthreads();

        // ---- pairwise squared distances + upper-triangle ----------------
        if (tid < 16) sm->sortbuf[496 + tid] = __int_as_float(0x7f800000);
        for (int p = tid; p < NP * NP; p += 256) {
            const int i = p >> 5, j = p & 31;
            float dsq = 0.0f;
#pragma unroll
            for (int d = 0; d < DD; d++) {
                float dx = X[i * DD + d] - X[j * DD + d];
                dsq = fmaf(dx, dx, dsq);
            }
            sm->dsq[p] = dsq;
            if (i < j) {
                const int t = i * NP - ((i * (i + 1)) >> 1) + (j - i - 1);
                sm->sortbuf[t] = dsq;
            }
        }
        __syncthreads();

        // ---- exact median: sort 512 (496 pair values + inf pad).
        // Multiset = 32 diag zeros + each pair twice; element 511 of 1024
        // maps to element (511-32)/2 = 239 of the sorted pairs.
        for (int k = 2; k <= 512; k <<= 1) {
            for (int j = k >> 1; j > 0; j >>= 1) {
                for (int t = tid; t < 512; t += 256) {
                    const int ixj = t ^ j;
                    if (ixj > t) {
                        float v0 = sm->sortbuf[t];
                        float v1 = sm->sortbuf[ixj];
                        const bool up = (t & k) == 0;
                        if ((v0 > v1) == up) {
                            sm->sortbuf[t] = v1;
                            sm->sortbuf[ixj] = v0;
                        }
                    }
                }
                __syncthreads();
            }
        }
        if (tid == 0) {
            const float med = sm->sortbuf[239];
            const float h = med / (2.0f * LOG_NP1);
            sm->gamma = 1.0f / (1e-8f + 2.0f * h);
        }
        __syncthreads();

        // ---- RBF phi / logp update (warp per 4 rows) --------------------
        {
            const float gamma = sm->gamma;
            const int nxt = cur ^ 1;
            for (int i = warp * 4; i < warp * 4 + 4; i++) {
                const int j = lane;
                float dx[DD];
#pragma unroll
                for (int d = 0; d < DD; d++)
                    dx[d] = X[i * DD + d] - X[j * DD + d];
                const float dsq = sm->dsq[i * NP + j];
                const float kap = __expf(-gamma * dsq);
                float red[8];
                float ds = 0.0f;
#pragma unroll
                for (int d = 0; d < DD; d++) {
                    red[d] = kap * (sm->s[j * DD + d] + 2.0f * gamma * dx[d]);
                    ds = fmaf(dx[d], sm->s[j * DD + d], ds);
                }
                red[6] = -2.0f * gamma * kap * ds;                   // line_4
                red[7] = 2.0f * gamma * dsq * kap - (float)DD * kap; // line_5
#pragma unroll
                for (int q = 0; q < 8; q++) {
#pragma unroll
                    for (int off = 16; off > 0; off >>= 1)
                        red[q] += __shfl_xor_sync(0xFFFFFFFFu, red[q], off);
                }
                if (lane == 0) {
#pragma unroll
                    for (int d = 0; d < DD; d++) {
                        const float phi = red[d] * (1.0f / (float)NP);
                        float xn = X[i * DD + d] + LRATE * phi;
                        xn = fminf(fmaxf(xn, -CLIP_LIM), CLIP_LIM);
                        sm->X[nxt][i * DD + d] = xn;
                    }
                    const float l4 = red[6] * (1.0f / (float)NP);
                    const float l5 = -2.0f * gamma * (red[7] * (1.0f / (float)NP));
                    sm->logp[i] -= LRATE * (l4 + l5);
                }
            }
        }
        cur ^= 1;
        __syncthreads();
    }

    // ---- write outputs: a (B*N*D) then logp (B*N) ------------------------
    for (int i = tid; i < NP * DD; i += 256)
        g_out[b * (NP * DD) + i] = sm->X[cur][i];
    if (tid < NP)
        g_out[BATCH * NP * DD + b * NP + tid] = sm->logp[tid];
}

// ---------------------------------------------------------------------------
extern "C" void kernel_launch(void* const* d_in, const int* in_sizes, int n_in,
                              void* d_out, int out_size) {
    const float* obs = (const float*)d_in[0];
    const float* a   = (const float*)d_in[1];
    const float* W1  = (const float*)d_in[2];
    const float* b1  = (const float*)d_in[3];
    const float* W2  = (const float*)d_in[4];
    const float* b2  = (const float*)d_in[5];
    const float* W3  = (const float*)d_in[6];
    // d_in[7] = b3: does not affect outputs — unused.
    float* out = (float*)d_out;

    transposeW2_kernel<<<dim3(8, 8), dim3(32, 8)>>>(W2);

    cudaFuncSetAttribute(svgd_kernel,
                         cudaFuncAttributeMaxDynamicSharedMemorySize,
                         (int)sizeof(Smem));
    svgd_kernel<<<BATCH, 256, sizeof(Smem)>>>(obs, a, W1, b1, W2, b2, W3, out);
}

// round 7
// speedup vs baseline: 1.5313x; 1.5313x over previous
#include <cuda_runtime.h>
#include <cuda_bf16.h>
#include <stdint.h>
#include <math.h>

#define BATCH 2048
#define NP 32
#define DD 6
#define NOBS 17
#define HID 256
#define NSTEPS 10
#define LRATE 0.1f
#define CLIP_LIM 1.0f
#define LOG_NP1 3.49650756f

// ---- pre-baked B-operand images (bf16 hi/lo pairs packed in u32) ----------
// Layout: chunk c holds k in [32c,32c+32); within chunk: row n (0..255) of 16
// u32 units (unit = bf16 pair (k,k+1)); unit index swizzled:
//   idx = c*4096 + n*16 + (kp ^ (((n>>1)&3)<<2)),  kp = (k%32)/2
__device__ unsigned g_BfH[32768], g_BfL[32768];   // fwd  B[n][k] = W2[k][n]
__device__ unsigned g_BbH[32768], g_BbL[32768];   // bwd  B[n][k] = W2[n][k]
__device__ unsigned g_W1H[4096],  g_W1L[4096];    // z1   B[n][k] = W1[k][n], K=32 pad
__device__ float g_W1xT[HID * DD];
__device__ unsigned short g_W3H[HID], g_W3L[HID];

__device__ __forceinline__ void split2(float v0, float v1, unsigned& hi, unsigned& lo) {
    __nv_bfloat16 h0 = __float2bfloat16(v0), h1 = __float2bfloat16(v1);
    float r0 = v0 - __bfloat162float(h0), r1 = v1 - __bfloat162float(h1);
    hi = (unsigned)__bfloat16_as_ushort(h0) | ((unsigned)__bfloat16_as_ushort(h1) << 16);
    lo = (unsigned)__bfloat16_as_ushort(__float2bfloat16(r0)) |
         ((unsigned)__bfloat16_as_ushort(__float2bfloat16(r1)) << 16);
}

__device__ __forceinline__ unsigned su32(const void* p) {
    unsigned a;
    asm("{ .reg .u64 t; cvta.to.shared.u64 t, %1; cvt.u32.u64 %0, t; }" : "=r"(a) : "l"(p));
    return a;
}
#define CPA16(d, s) asm volatile("cp.async.cg.shared.global [%0], [%1], 16;" :: "r"(d), "l"(s))
#define CPC()       asm volatile("cp.async.commit_group;" ::: "memory")
#define CPW()       asm volatile("cp.async.wait_group 0;" ::: "memory")

__device__ __forceinline__ void mma16816(float* c, const unsigned* a, unsigned b0, unsigned b1) {
    asm volatile(
        "mma.sync.aligned.m16n8k16.row.col.f32.bf16.bf16.f32 "
        "{%0,%1,%2,%3}, {%4,%5,%6,%7}, {%8,%9}, {%0,%1,%2,%3};"
        : "+f"(c[0]), "+f"(c[1]), "+f"(c[2]), "+f"(c[3])
        : "r"(a[0]), "r"(a[1]), "r"(a[2]), "r"(a[3]), "r"(b0), "r"(b1));
}

// ---- prep: bake weight images --------------------------------------------
__global__ void prep_kernel(const float* __restrict__ W1, const float* __restrict__ W2,
                            const float* __restrict__ W3) {
    const int t = blockIdx.x * 256 + threadIdx.x;   // 128 blocks x 256
    const int n = t >> 7, kp = t & 127, k = kp * 2;
    const int idx = (kp >> 4) * 4096 + n * 16 + ((kp & 15) ^ (((n >> 1) & 3) << 2));
    unsigned hi, lo;
    split2(W2[k * 256 + n], W2[(k + 1) * 256 + n], hi, lo);   // fwd
    g_BfH[idx] = hi; g_BfL[idx] = lo;
    split2(W2[n * 256 + k], W2[n * 256 + k + 1], hi, lo);     // bwd
    g_BbH[idx] = hi; g_BbL[idx] = lo;
    if (kp < 16) {
        float v0 = (k < 23) ? W1[k * 256 + n] : 0.0f;
        float v1 = (k + 1 < 23) ? W1[(k + 1) * 256 + n] : 0.0f;
        split2(v0, v1, hi, lo);
        const int i2 = n * 16 + (kp ^ (((n >> 1) & 3) << 2));
        g_W1H[i2] = hi; g_W1L[i2] = lo;
    }
    if (kp < 6) g_W1xT[n * 6 + kp] = W1[(17 + kp) * 256 + n];
    if (kp == 0) {
        __nv_bfloat16 h = __float2bfloat16(W3[n]);
        g_W3H[n] = __bfloat16_as_ushort(h);
        g_W3L[n] = __bfloat16_as_ushort(__float2bfloat16(W3[n] - __bfloat162float(h)));
    }
}

// ---- shared memory --------------------------------------------------------
// A images: [m 0..127][unit kp 0..127], idx = m*128 + (kp ^ ((m&7)<<2))
struct __align__(16) SM {
    unsigned Ah[16384], Al[16384];      // 64KB + 64KB
    unsigned Bh[4096],  Bl[4096];       // 16KB + 16KB chunk buffers
    float X[2][128 * 6];
    float s[128 * 6];
    float spart[128 * 6 * 4];
    float sortbuf[4 * 512];
    float W1xT[256 * 6];
    float b1[256], b2[256];
    float logp[128];
    float gamma[4];
    unsigned short W3H[256], W3L[256];
};

extern __shared__ char smraw[];

template <int NCHUNK>
__device__ __forceinline__ void gemm_mma(SM* sm, const unsigned* __restrict__ gBh,
                                         const unsigned* __restrict__ gBl,
                                         float acc[2][8][4], int m0, int n0,
                                         int lane, int tid) {
#pragma unroll
    for (int i = 0; i < 2; i++)
#pragma unroll
        for (int j = 0; j < 8; j++)
#pragma unroll
            for (int e = 0; e < 4; e++) acc[i][j][e] = 0.0f;
    const int swA = (lane >> 2) << 2;
    const unsigned dH = su32(sm->Bh), dL = su32(sm->Bl);
    for (int ch = 0; ch < NCHUNK; ch++) {
        const char* sH = (const char*)(gBh + ch * 4096);
        const char* sL = (const char*)(gBl + ch * 4096);
        for (int i = tid; i < 1024; i += 512) {
            CPA16(dH + i * 16, sH + i * 16);
            CPA16(dL + i * 16, sL + i * 16);
        }
        CPC(); CPW();
        __syncthreads();
#pragma unroll
        for (int pass = 0; pass < 3; pass++) {
            const unsigned* A = (pass == 2) ? sm->Al : sm->Ah;
            const unsigned* B = (pass == 1) ? sm->Bl : sm->Bh;
#pragma unroll
            for (int ks = 0; ks < 2; ks++) {
                const int kpb = ch * 16 + ks * 8 + (lane & 3);
                const int kpl = ks * 8 + (lane & 3);
                unsigned af[2][4];
#pragma unroll
                for (int mt = 0; mt < 2; mt++) {
                    const int r = m0 + mt * 16 + (lane >> 2);
                    af[mt][0] = A[r * 128 + (kpb ^ swA)];
                    af[mt][1] = A[(r + 8) * 128 + (kpb ^ swA)];
                    af[mt][2] = A[r * 128 + ((kpb + 4) ^ swA)];
                    af[mt][3] = A[(r + 8) * 128 + ((kpb + 4) ^ swA)];
                }
#pragma unroll
                for (int nt = 0; nt < 8; nt++) {
                    const int n = n0 + nt * 8 + (lane >> 2);
                    const int swb = ((n >> 1) & 3) << 2;
                    const unsigned b0 = B[n * 16 + (kpl ^ swb)];
                    const unsigned b1 = B[n * 16 + ((kpl + 4) ^ swb)];
                    mma16816(acc[0][nt], af[0], b0, b1);
                    mma16816(acc[1][nt], af[1], b0, b1);
                }
            }
        }
        __syncthreads();
    }
}

__global__ void __launch_bounds__(512, 1) svgd_kernel(
    const float* __restrict__ g_obs, const float* __restrict__ g_a,
    const float* __restrict__ g_b1, const float* __restrict__ g_b2,
    float* __restrict__ g_out)
{
    SM* sm = (SM*)smraw;
    const int tid = threadIdx.x, bx = blockIdx.x;
    const int warp = tid >> 5, lane = tid & 31;
    const int m0 = (warp & 3) * 32;          // warp row tile
    const int wN = warp >> 2;                // warp col group
    const int n0 = wN * 64;
    const int swA = (lane >> 2) << 2;

    // ---- prologue ---------------------------------------------------------
    if (tid < 256) {
        sm->b1[tid] = g_b1[tid];
        sm->b2[tid] = g_b2[tid];
        sm->W3H[tid] = g_W3H[tid];
        sm->W3L[tid] = g_W3L[tid];
    }
    for (int i = tid; i < 1536; i += 512) sm->W1xT[i] = g_W1xT[i];
    for (int i = tid; i < 768; i += 512) sm->X[0][i] = g_a[bx * 768 + i];
    if (tid < 128) sm->logp[tid] = 0.0f;
    __syncthreads();

    int cur = 0;
    float acc[2][8][4];
    unsigned mk[2];

    for (int step = 0; step < NSTEPS; step++) {
        // ---- build z1 A image: obs + X + pad (kp 0..15) -----------------
        for (int idx = tid; idx < 128 * 16; idx += 512) {
            const int row = idx >> 4, kp = idx & 15, k0 = kp * 2;
            float v0, v1;
            v0 = (k0 < NOBS) ? g_obs[(bx * 128 + row) * NOBS + k0]
               : (k0 < 23)   ? sm->X[cur][row * 6 + k0 - NOBS] : 0.0f;
            const int k1 = k0 + 1;
            v1 = (k1 < NOBS) ? g_obs[(bx * 128 + row) * NOBS + k1]
               : (k1 < 23)   ? sm->X[cur][row * 6 + k1 - NOBS] : 0.0f;
            unsigned hi, lo;
            split2(v0, v1, hi, lo);
            const int o = row * 128 + (kp ^ ((row & 7) << 2));
            sm->Ah[o] = hi; sm->Al[o] = lo;
        }
        // (gemm's first barrier orders these writes)

        // ---- z1 GEMM + epilogue: h1 = relu(z1+b1), mask, split ----------
        gemm_mma<1>(sm, g_W1H, g_W1L, acc, m0, n0, lane, tid);
        mk[0] = 0u; mk[1] = 0u;
#pragma unroll
        for (int mt = 0; mt < 2; mt++) {
            const int rA = m0 + mt * 16 + (lane >> 2);
#pragma unroll
            for (int nt = 0; nt < 8; nt++) {
                const int cA = n0 + nt * 8 + ((lane & 3) << 1);
                const int kp = cA >> 1;
                float h0 = fmaxf(acc[mt][nt][0] + sm->b1[cA], 0.0f);
                float h1 = fmaxf(acc[mt][nt][1] + sm->b1[cA + 1], 0.0f);
                float h2 = fmaxf(acc[mt][nt][2] + sm->b1[cA], 0.0f);
                float h3 = fmaxf(acc[mt][nt][3] + sm->b1[cA + 1], 0.0f);
                if (h0 > 0.0f) mk[mt] |= 1u << (nt * 4 + 0);
                if (h1 > 0.0f) mk[mt] |= 1u << (nt * 4 + 1);
                if (h2 > 0.0f) mk[mt] |= 1u << (nt * 4 + 2);
                if (h3 > 0.0f) mk[mt] |= 1u << (nt * 4 + 3);
                unsigned hi, lo;
                split2(h0, h1, hi, lo);
                int o = rA * 128 + (kp ^ swA);
                sm->Ah[o] = hi; sm->Al[o] = lo;
                split2(h2, h3, hi, lo);
                o = (rA + 8) * 128 + (kp ^ swA);
                sm->Ah[o] = hi; sm->Al[o] = lo;
            }
        }

        // ---- fwd GEMM (z2) + epilogue: dz2 = (z2+b2>0)*W3 ---------------
        gemm_mma<8>(sm, g_BfH, g_BfL, acc, m0, n0, lane, tid);
#pragma unroll
        for (int mt = 0; mt < 2; mt++) {
            const int rA = m0 + mt * 16 + (lane >> 2);
#pragma unroll
            for (int nt = 0; nt < 8; nt++) {
                const int cA = n0 + nt * 8 + ((lane & 3) << 1);
                const int kp = cA >> 1;
                const bool s0 = acc[mt][nt][0] + sm->b2[cA] > 0.0f;
                const bool s1 = acc[mt][nt][1] + sm->b2[cA + 1] > 0.0f;
                const bool s2 = acc[mt][nt][2] + sm->b2[cA] > 0.0f;
                const bool s3 = acc[mt][nt][3] + sm->b2[cA + 1] > 0.0f;
                const unsigned h0 = s0 ? sm->W3H[cA] : 0, h1 = s1 ? sm->W3H[cA + 1] : 0;
                const unsigned h2 = s2 ? sm->W3H[cA] : 0, h3 = s3 ? sm->W3H[cA + 1] : 0;
                const unsigned l0 = s0 ? sm->W3L[cA] : 0, l1 = s1 ? sm->W3L[cA + 1] : 0;
                const unsigned l2 = s2 ? sm->W3L[cA] : 0, l3 = s3 ? sm->W3L[cA + 1] : 0;
                int o = rA * 128 + (kp ^ swA);
                sm->Ah[o] = h0 | (h1 << 16); sm->Al[o] = l0 | (l1 << 16);
                o = (rA + 8) * 128 + (kp ^ swA);
                sm->Ah[o] = h2 | (h3 << 16); sm->Al[o] = l2 | (l3 << 16);
            }
        }

        // ---- bwd GEMM (dz1) + epilogue: mask + fold score matmul --------
        gemm_mma<8>(sm, g_BbH, g_BbL, acc, m0, n0, lane, tid);
        {
            float sp[4][6];
#pragma unroll
            for (int s = 0; s < 4; s++)
#pragma unroll
                for (int d = 0; d < 6; d++) sp[s][d] = 0.0f;
#pragma unroll
            for (int mt = 0; mt < 2; mt++)
#pragma unroll
                for (int nt = 0; nt < 8; nt++)
#pragma unroll
                    for (int e = 0; e < 4; e++) {
                        if ((mk[mt] >> (nt * 4 + e)) & 1u) {
                            const float v = acc[mt][nt][e];
                            const int c = n0 + nt * 8 + ((lane & 3) << 1) + (e & 1);
                            const int s = mt * 2 + (e >> 1);
                            const float* w = &sm->W1xT[c * 6];
#pragma unroll
                            for (int d = 0; d < 6; d++) sp[s][d] = fmaf(v, w[d], sp[s][d]);
                        }
                    }
#pragma unroll
            for (int s = 0; s < 4; s++)
#pragma unroll
                for (int d = 0; d < 6; d++) {
                    sp[s][d] += __shfl_xor_sync(0xFFFFFFFFu, sp[s][d], 1);
                    sp[s][d] += __shfl_xor_sync(0xFFFFFFFFu, sp[s][d], 2);
                }
            if ((lane & 3) == 0) {
#pragma unroll
                for (int s = 0; s < 4; s++) {
                    const int row = m0 + (s >> 1) * 16 + (s & 1) * 8 + (lane >> 2);
#pragma unroll
                    for (int d = 0; d < 6; d++)
                        sm->spart[(row * 6 + d) * 4 + wN] = sp[s][d];
                }
            }
        }
        __syncthreads();
        for (int i = tid; i < 768; i += 512)
            sm->s[i] = sm->spart[4 * i] + sm->spart[4 * i + 1] +
                       sm->spart[4 * i + 2] + sm->spart[4 * i + 3];

        // ---- pairwise dist upper-triangle (4 groups of 128 threads) -----
        {
            const int g = tid >> 7, t0 = tid & 127;
            const float* Xg = &sm->X[cur][g * 192];
            float* sb = &sm->sortbuf[g * 512];
            if (t0 < 16) sb[496 + t0] = __int_as_float(0x7f800000);
            for (int p = t0; p < 1024; p += 128) {
                const int i = p >> 5, j = p & 31;
                if (i < j) {
                    float ds = 0.0f;
#pragma unroll
                    for (int d = 0; d < 6; d++) {
                        float dx = Xg[i * 6 + d] - Xg[j * 6 + d];
                        ds = fmaf(dx, dx, ds);
                    }
                    sb[i * 32 - ((i * (i + 1)) >> 1) + (j - i - 1)] = ds;
                }
            }
        }
        __syncthreads();
        // ---- 4 concurrent bitonic sorts of 512; median idx 239 ----------
        {
            const int g = tid >> 7, t0 = tid & 127;
            float* sb = &sm->sortbuf[g * 512];
            for (int k = 2; k <= 512; k <<= 1)
                for (int j = k >> 1; j > 0; j >>= 1) {
                    for (int t = t0; t < 512; t += 128) {
                        const int x = t ^ j;
                        if (x > t) {
                            float v0 = sb[t], v1 = sb[x];
                            if ((v0 > v1) == ((t & k) == 0)) { sb[t] = v1; sb[x] = v0; }
                        }
                    }
                    __syncthreads();
                }
            if (t0 == 0) {
                const float hm = sb[239] / (2.0f * LOG_NP1);
                sm->gamma[g] = 1.0f / (1e-8f + 2.0f * hm);
            }
        }
        __syncthreads();
        // ---- RBF phi / logp (4 warps per batch, 8 rows per warp) --------
        {
            const int g = warp >> 2, rb = (warp & 3) * 8;
            const float gamma = sm->gamma[g];
            const float* Xg = &sm->X[cur][g * 192];
            float* Xn = &sm->X[cur ^ 1][g * 192];
            const float* sg = &sm->s[g * 192];
            for (int ii = 0; ii < 8; ii++) {
                const int i = rb + ii, j = lane;
                float dx[6], red[8], ds = 0.0f, dsq = 0.0f;
#pragma unroll
                for (int d = 0; d < 6; d++) {
                    dx[d] = Xg[i * 6 + d] - Xg[j * 6 + d];
                    dsq = fmaf(dx[d], dx[d], dsq);
                }
                const float kap = __expf(-gamma * dsq);
#pragma unroll
                for (int d = 0; d < 6; d++) {
                    red[d] = kap * (sg[j * 6 + d] + 2.0f * gamma * dx[d]);
                    ds = fmaf(dx[d], sg[j * 6 + d], ds);
                }
                red[6] = -2.0f * gamma * kap * ds;
                red[7] = 2.0f * gamma * dsq * kap - 6.0f * kap;
#pragma unroll
                for (int q = 0; q < 8; q++)
#pragma unroll
                    for (int off = 16; off > 0; off >>= 1)
                        red[q] += __shfl_xor_sync(0xFFFFFFFFu, red[q], off);
                if (lane == 0) {
#pragma unroll
                    for (int d = 0; d < 6; d++) {
                        float xn = Xg[i * 6 + d] + LRATE * (red[d] * (1.0f / 32.0f));
                        Xn[i * 6 + d] = fminf(fmaxf(xn, -CLIP_LIM), CLIP_LIM);
                    }
                    const float l4 = red[6] * (1.0f / 32.0f);
                    const float l5 = -2.0f * gamma * (red[7] * (1.0f / 32.0f));
                    sm->logp[g * 32 + i] -= LRATE * (l4 + l5);
                }
            }
        }
        cur ^= 1;
        __syncthreads();
    }

    // ---- outputs ----------------------------------------------------------
    for (int i = tid; i < 768; i += 512) g_out[bx * 768 + i] = sm->X[cur][i];
    if (tid < 128) g_out[BATCH * NP * DD + bx * 128 + tid] = sm->logp[tid];
}

// ---------------------------------------------------------------------------
extern "C" void kernel_launch(void* const* d_in, const int* in_sizes, int n_in,
                              void* d_out, int out_size) {
    const float* obs = (const float*)d_in[0];
    const float* a   = (const float*)d_in[1];
    const float* W1  = (const float*)d_in[2];
    const float* b1  = (const float*)d_in[3];
    const float* W2  = (const float*)d_in[4];
    const float* b2  = (const float*)d_in[5];
    const float* W3  = (const float*)d_in[6];
    // d_in[7] = b3: unused (does not affect gradients/outputs)
    float* out = (float*)d_out;

    prep_kernel<<<128, 256>>>(W1, W2, W3);
    cudaFuncSetAttribute(svgd_kernel, cudaFuncAttributeMaxDynamicSharedMemorySize,
                         (int)sizeof(SM));
    svgd_kernel<<<512, 512, sizeof(SM)>>>(obs, a, b1, b2, out);
}

// round 9
// speedup vs baseline: 1.7833x; 1.1646x over previous
#include <cuda_runtime.h>
#include <cuda_bf16.h>
#include <stdint.h>
#include <math.h>

#define BATCH 2048
#define NP 32
#define DD 6
#define NOBS 17
#define HID 256
#define NSTEPS 10
#define LRATE 0.1f
#define CLIP_LIM 1.0f
#define LOG_NP1 3.49650756f

// ---- pre-baked B-operand images (bf16 hi/lo pairs packed in u32) ----------
// Layout: chunk c holds k in [32c,32c+32); within chunk: row n (0..255) of 16
// u32 units (unit = bf16 pair (k,k+1)); unit index swizzled:
//   idx = c*4096 + n*16 + (kp ^ (((n>>1)&3)<<2)),  kp = (k%32)/2
__device__ unsigned g_BfH[32768], g_BfL[32768];   // fwd  B[n][k] = W2[k][n]
__device__ unsigned g_BbH[32768], g_BbL[32768];   // bwd  B[n][k] = W2[n][k]
__device__ unsigned g_W1H[4096],  g_W1L[4096];    // z1   B[n][k] = W1[k][n], K=32 pad
__device__ float g_W1xT[HID * DD];
__device__ unsigned short g_W3H[HID], g_W3L[HID];

__device__ __forceinline__ void split2(float v0, float v1, unsigned& hi, unsigned& lo) {
    __nv_bfloat16 h0 = __float2bfloat16(v0), h1 = __float2bfloat16(v1);
    float r0 = v0 - __bfloat162float(h0), r1 = v1 - __bfloat162float(h1);
    hi = (unsigned)__bfloat16_as_ushort(h0) | ((unsigned)__bfloat16_as_ushort(h1) << 16);
    lo = (unsigned)__bfloat16_as_ushort(__float2bfloat16(r0)) |
         ((unsigned)__bfloat16_as_ushort(__float2bfloat16(r1)) << 16);
}

__device__ __forceinline__ unsigned su32(const void* p) {
    unsigned a;
    asm("{ .reg .u64 t; cvta.to.shared.u64 t, %1; cvt.u32.u64 %0, t; }" : "=r"(a) : "l"(p));
    return a;
}
#define CPA16(d, s) asm volatile("cp.async.cg.shared.global [%0], [%1], 16;" :: "r"(d), "l"(s))
#define CPC()       asm volatile("cp.async.commit_group;" ::: "memory")
#define CPW0()      asm volatile("cp.async.wait_group 0;" ::: "memory")
#define CPW1()      asm volatile("cp.async.wait_group 1;" ::: "memory")

__device__ __forceinline__ void mma16816(float* c, const unsigned* a, unsigned b0, unsigned b1) {
    asm volatile(
        "mma.sync.aligned.m16n8k16.row.col.f32.bf16.bf16.f32 "
        "{%0,%1,%2,%3}, {%4,%5,%6,%7}, {%8,%9}, {%0,%1,%2,%3};"
        : "+f"(c[0]), "+f"(c[1]), "+f"(c[2]), "+f"(c[3])
        : "r"(a[0]), "r"(a[1]), "r"(a[2]), "r"(a[3]), "r"(b0), "r"(b1));
}

// ---- prep: bake weight images --------------------------------------------
__global__ void prep_kernel(const float* __restrict__ W1, const float* __restrict__ W2,
                            const float* __restrict__ W3) {
    const int t = blockIdx.x * 256 + threadIdx.x;   // 128 blocks x 256
    const int n = t >> 7, kp = t & 127, k = kp * 2;
    const int idx = (kp >> 4) * 4096 + n * 16 + ((kp & 15) ^ (((n >> 1) & 3) << 2));
    unsigned hi, lo;
    split2(W2[k * 256 + n], W2[(k + 1) * 256 + n], hi, lo);   // fwd
    g_BfH[idx] = hi; g_BfL[idx] = lo;
    split2(W2[n * 256 + k], W2[n * 256 + k + 1], hi, lo);     // bwd
    g_BbH[idx] = hi; g_BbL[idx] = lo;
    if (kp < 16) {
        float v0 = (k < 23) ? W1[k * 256 + n] : 0.0f;
        float v1 = (k + 1 < 23) ? W1[(k + 1) * 256 + n] : 0.0f;
        split2(v0, v1, hi, lo);
        const int i2 = n * 16 + (kp ^ (((n >> 1) & 3) << 2));
        g_W1H[i2] = hi; g_W1L[i2] = lo;
    }
    if (kp < 6) g_W1xT[n * 6 + kp] = W1[(17 + kp) * 256 + n];
    if (kp == 0) {
        __nv_bfloat16 h = __float2bfloat16(W3[n]);
        g_W3H[n] = __bfloat16_as_ushort(h);
        g_W3L[n] = __bfloat16_as_ushort(__float2bfloat16(W3[n] - __bfloat162float(h)));
    }
}

// ---- shared memory --------------------------------------------------------
// A images: [m 0..127][unit kp 0..127], idx = m*128 + (kp ^ ((m&7)<<2))
// scratch is time-multiplexed: spart[3072] (bwd epilogue) then sortbuf[2048].
// Total: 131072 + 65536 + 6144 + 3072 + 12288 + 6144 + 2048 + 512 + 16 + 1024
//      = 227,856 B <= 232,448 B (227 KB) dynamic smem ceiling.
struct __align__(16) SM {
    unsigned Ah[16384], Al[16384];          // 64KB + 64KB
    unsigned Bh[2][4096], Bl[2][4096];      // double-buffered 16KB chunks
    float X[2][128 * 6];
    float s[128 * 6];
    float scratch[128 * 6 * 4];             // spart / sortbuf (time-shared)
    float W1xT[256 * 6];
    float b1[256], b2[256];
    float logp[128];
    float gamma[4];
    unsigned short W3H[256], W3L[256];
};

extern __shared__ char smraw[];

__device__ __forceinline__ void issue_chunk(SM* sm, int buf,
                                            const unsigned* __restrict__ gBh,
                                            const unsigned* __restrict__ gBl,
                                            int ch, int tid) {
    const unsigned dH = su32(sm->Bh[buf]), dL = su32(sm->Bl[buf]);
    const char* sH = (const char*)(gBh + ch * 4096);
    const char* sL = (const char*)(gBl + ch * 4096);
    for (int i = tid; i < 1024; i += 512) {
        CPA16(dH + i * 16, sH + i * 16);
        CPA16(dL + i * 16, sL + i * 16);
    }
    CPC();
}

// Double-buffered GEMM: M=128, N=256, K = 32*NCHUNK, bf16x3.
template <int NCHUNK>
__device__ __forceinline__ void gemm_mma(SM* sm, const unsigned* __restrict__ gBh,
                                         const unsigned* __restrict__ gBl,
                                         float acc[2][8][4], int m0, int n0,
                                         int lane, int tid) {
#pragma unroll
    for (int i = 0; i < 2; i++)
#pragma unroll
        for (int j = 0; j < 8; j++)
#pragma unroll
            for (int e = 0; e < 4; e++) acc[i][j][e] = 0.0f;
    const int swA = (lane >> 2) << 2;

    issue_chunk(sm, 0, gBh, gBl, 0, tid);
    for (int ch = 0; ch < NCHUNK; ch++) {
        __syncthreads();            // buffer (ch+1)&1 free: its readers finished
        if (ch + 1 < NCHUNK) {
            issue_chunk(sm, (ch + 1) & 1, gBh, gBl, ch + 1, tid);
            CPW1();                 // chunk ch complete; ch+1 still in flight
        } else {
            CPW0();
        }
        __syncthreads();            // chunk ch visible to all warps
        const unsigned* Bhc = sm->Bh[ch & 1];
        const unsigned* Blc = sm->Bl[ch & 1];
#pragma unroll
        for (int pass = 0; pass < 3; pass++) {
            const unsigned* A = (pass == 2) ? sm->Al : sm->Ah;
            const unsigned* B = (pass == 1) ? Blc : Bhc;
#pragma unroll
            for (int ks = 0; ks < 2; ks++) {
                const int kpb = ch * 16 + ks * 8 + (lane & 3);
                const int kpl = ks * 8 + (lane & 3);
                unsigned af[2][4];
#pragma unroll
                for (int mt = 0; mt < 2; mt++) {
                    const int r = m0 + mt * 16 + (lane >> 2);
                    af[mt][0] = A[r * 128 + (kpb ^ swA)];
                    af[mt][1] = A[(r + 8) * 128 + (kpb ^ swA)];
                    af[mt][2] = A[r * 128 + ((kpb + 4) ^ swA)];
                    af[mt][3] = A[(r + 8) * 128 + ((kpb + 4) ^ swA)];
                }
#pragma unroll
                for (int nt = 0; nt < 8; nt++) {
                    const int n = n0 + nt * 8 + (lane >> 2);
                    const int swb = ((n >> 1) & 3) << 2;
                    const unsigned b0 = B[n * 16 + (kpl ^ swb)];
                    const unsigned b1 = B[n * 16 + ((kpl + 4) ^ swb)];
                    mma16816(acc[0][nt], af[0], b0, b1);
                    mma16816(acc[1][nt], af[1], b0, b1);
                }
            }
        }
    }
    __syncthreads();                // A-image readers done before epilogue writes
}

__global__ void __launch_bounds__(512, 1) svgd_kernel(
    const float* __restrict__ g_obs, const float* __restrict__ g_a,
    const float* __restrict__ g_b1, const float* __restrict__ g_b2,
    float* __restrict__ g_out)
{
    SM* sm = (SM*)smraw;
    const int tid = threadIdx.x, bx = blockIdx.x;
    const int warp = tid >> 5, lane = tid & 31;
    const int m0 = (warp & 3) * 32;          // warp row tile
    const int wN = warp >> 2;                // warp col group
    const int n0 = wN * 64;
    const int swA = (lane >> 2) << 2;

    // ---- prologue ---------------------------------------------------------
    if (tid < 256) {
        sm->b1[tid] = g_b1[tid];
        sm->b2[tid] = g_b2[tid];
        sm->W3H[tid] = g_W3H[tid];
        sm->W3L[tid] = g_W3L[tid];
    }
    for (int i = tid; i < 1536; i += 512) sm->W1xT[i] = g_W1xT[i];
    for (int i = tid; i < 768; i += 512) sm->X[0][i] = g_a[bx * 768 + i];
    if (tid < 128) sm->logp[tid] = 0.0f;
    __syncthreads();

    int cur = 0;
    float acc[2][8][4];
    unsigned mk[2];

    for (int step = 0; step < NSTEPS; step++) {
        // ---- build z1 A image: obs + X + pad (kp 0..15) -----------------
        for (int idx = tid; idx < 128 * 16; idx += 512) {
            const int row = idx >> 4, kp = idx & 15, k0 = kp * 2;
            float v0, v1;
            v0 = (k0 < NOBS) ? g_obs[(bx * 128 + row) * NOBS + k0]
               : (k0 < 23)   ? sm->X[cur][row * 6 + k0 - NOBS] : 0.0f;
            const int k1 = k0 + 1;
            v1 = (k1 < NOBS) ? g_obs[(bx * 128 + row) * NOBS + k1]
               : (k1 < 23)   ? sm->X[cur][row * 6 + k1 - NOBS] : 0.0f;
            unsigned hi, lo;
            split2(v0, v1, hi, lo);
            const int o = row * 128 + (kp ^ ((row & 7) << 2));
            sm->Ah[o] = hi; sm->Al[o] = lo;
        }
        // (gemm's first barriers order these writes before MMA reads)

        // ---- z1 GEMM + epilogue: h1 = relu(z1+b1), mask, split ----------
        gemm_mma<1>(sm, g_W1H, g_W1L, acc, m0, n0, lane, tid);
        mk[0] = 0u; mk[1] = 0u;
#pragma unroll
        for (int mt = 0; mt < 2; mt++) {
            const int rA = m0 + mt * 16 + (lane >> 2);
#pragma unroll
            for (int nt = 0; nt < 8; nt++) {
                const int cA = n0 + nt * 8 + ((lane & 3) << 1);
                const int kp = cA >> 1;
                float h0 = fmaxf(acc[mt][nt][0] + sm->b1[cA], 0.0f);
                float h1 = fmaxf(acc[mt][nt][1] + sm->b1[cA + 1], 0.0f);
                float h2 = fmaxf(acc[mt][nt][2] + sm->b1[cA], 0.0f);
                float h3 = fmaxf(acc[mt][nt][3] + sm->b1[cA + 1], 0.0f);
                if (h0 > 0.0f) mk[mt] |= 1u << (nt * 4 + 0);
                if (h1 > 0.0f) mk[mt] |= 1u << (nt * 4 + 1);
                if (h2 > 0.0f) mk[mt] |= 1u << (nt * 4 + 2);
                if (h3 > 0.0f) mk[mt] |= 1u << (nt * 4 + 3);
                unsigned hi, lo;
                split2(h0, h1, hi, lo);
                int o = rA * 128 + (kp ^ swA);
                sm->Ah[o] = hi; sm->Al[o] = lo;
                split2(h2, h3, hi, lo);
                o = (rA + 8) * 128 + (kp ^ swA);
                sm->Ah[o] = hi; sm->Al[o] = lo;
            }
        }

        // ---- fwd GEMM (z2) + epilogue: dz2 = (z2+b2>0)*W3 ---------------
        gemm_mma<8>(sm, g_BfH, g_BfL, acc, m0, n0, lane, tid);
#pragma unroll
        for (int mt = 0; mt < 2; mt++) {
            const int rA = m0 + mt * 16 + (lane >> 2);
#pragma unroll
            for (int nt = 0; nt < 8; nt++) {
                const int cA = n0 + nt * 8 + ((lane & 3) << 1);
                const int kp = cA >> 1;
                const bool s0 = acc[mt][nt][0] + sm->b2[cA] > 0.0f;
                const bool s1 = acc[mt][nt][1] + sm->b2[cA + 1] > 0.0f;
                const bool s2 = acc[mt][nt][2] + sm->b2[cA] > 0.0f;
                const bool s3 = acc[mt][nt][3] + sm->b2[cA + 1] > 0.0f;
                const unsigned h0 = s0 ? sm->W3H[cA] : 0, h1 = s1 ? sm->W3H[cA + 1] : 0;
                const unsigned h2 = s2 ? sm->W3H[cA] : 0, h3 = s3 ? sm->W3H[cA + 1] : 0;
                const unsigned l0 = s0 ? sm->W3L[cA] : 0, l1 = s1 ? sm->W3L[cA + 1] : 0;
                const unsigned l2 = s2 ? sm->W3L[cA] : 0, l3 = s3 ? sm->W3L[cA + 1] : 0;
                int o = rA * 128 + (kp ^ swA);
                sm->Ah[o] = h0 | (h1 << 16); sm->Al[o] = l0 | (l1 << 16);
                o = (rA + 8) * 128 + (kp ^ swA);
                sm->Ah[o] = h2 | (h3 << 16); sm->Al[o] = l2 | (l3 << 16);
            }
        }

        // ---- bwd GEMM (dz1) + epilogue: mask + fold score matmul --------
        gemm_mma<8>(sm, g_BbH, g_BbL, acc, m0, n0, lane, tid);
        {
            float sp[4][6];
#pragma unroll
            for (int s = 0; s < 4; s++)
#pragma unroll
                for (int d = 0; d < 6; d++) sp[s][d] = 0.0f;
#pragma unroll
            for (int mt = 0; mt < 2; mt++)
#pragma unroll
                for (int nt = 0; nt < 8; nt++)
#pragma unroll
                    for (int e = 0; e < 4; e++) {
                        if ((mk[mt] >> (nt * 4 + e)) & 1u) {
                            const float v = acc[mt][nt][e];
                            const int c = n0 + nt * 8 + ((lane & 3) << 1) + (e & 1);
                            const int s = mt * 2 + (e >> 1);
                            const float* w = &sm->W1xT[c * 6];
#pragma unroll
                            for (int d = 0; d < 6; d++) sp[s][d] = fmaf(v, w[d], sp[s][d]);
                        }
                    }
#pragma unroll
            for (int s = 0; s < 4; s++)
#pragma unroll
                for (int d = 0; d < 6; d++) {
                    sp[s][d] += __shfl_xor_sync(0xFFFFFFFFu, sp[s][d], 1);
                    sp[s][d] += __shfl_xor_sync(0xFFFFFFFFu, sp[s][d], 2);
                }
            if ((lane & 3) == 0) {
#pragma unroll
                for (int s = 0; s < 4; s++) {
                    const int row = m0 + (s >> 1) * 16 + (s & 1) * 8 + (lane >> 2);
#pragma unroll
                    for (int d = 0; d < 6; d++)
                        sm->scratch[(row * 6 + d) * 4 + wN] = sp[s][d];
                }
            }
        }
        __syncthreads();
        for (int i = tid; i < 768; i += 512)
            sm->s[i] = sm->scratch[4 * i] + sm->scratch[4 * i + 1] +
                       sm->scratch[4 * i + 2] + sm->scratch[4 * i + 3];
        __syncthreads();    // scratch (spart) reads done before sortbuf writes

        // ---- pairwise dist upper-triangle (4 groups of 128 threads) -----
        {
            const int g = tid >> 7, t0 = tid & 127;
            const float* Xg = &sm->X[cur][g * 192];
            float* sb = &sm->scratch[g * 512];
            if (t0 < 16) sb[496 + t0] = __int_as_float(0x7f800000);
            for (int p = t0; p < 1024; p += 128) {
                const int i = p >> 5, j = p & 31;
                if (i < j) {
                    float ds = 0.0f;
#pragma unroll
                    for (int d = 0; d < 6; d++) {
                        float dx = Xg[i * 6 + d] - Xg[j * 6 + d];
                        ds = fmaf(dx, dx, ds);
                    }
                    sb[i * 32 - ((i * (i + 1)) >> 1) + (j - i - 1)] = ds;
                }
            }
        }
        __syncthreads();
        // ---- 4 concurrent bitonic sorts of 512; median idx 239 ----------
        {
            const int g = tid >> 7, t0 = tid & 127;
            float* sb = &sm->scratch[g * 512];
            for (int k = 2; k <= 512; k <<= 1)
                for (int j = k >> 1; j > 0; j >>= 1) {
                    for (int t = t0; t < 512; t += 128) {
                        const int x = t ^ j;
                        if (x > t) {
                            float v0 = sb[t], v1 = sb[x];
                            if ((v0 > v1) == ((t & k) == 0)) { sb[t] = v1; sb[x] = v0; }
                        }
                    }
                    __syncthreads();
                }
            if (t0 == 0) {
                const float hm = sb[239] / (2.0f * LOG_NP1);
                sm->gamma[g] = 1.0f / (1e-8f + 2.0f * hm);
            }
        }
        __syncthreads();
        // ---- RBF phi / logp (4 warps per batch, 8 rows per warp) --------
        {
            const int g = warp >> 2, rb = (warp & 3) * 8;
            const float gamma = sm->gamma[g];
            const float* Xg = &sm->X[cur][g * 192];
            float* Xn = &sm->X[cur ^ 1][g * 192];
            const float* sg = &sm->s[g * 192];
            for (int ii = 0; ii < 8; ii++) {
                const int i = rb + ii, j = lane;
                float dx[6], red[8], ds = 0.0f, dsq = 0.0f;
#pragma unroll
                for (int d = 0; d < 6; d++) {
                    dx[d] = Xg[i * 6 + d] - Xg[j * 6 + d];
                    dsq = fmaf(dx[d], dx[d], dsq);
                }
                const float kap = __expf(-gamma * dsq);
#pragma unroll
                for (int d = 0; d < 6; d++) {
                    red[d] = kap * (sg[j * 6 + d] + 2.0f * gamma * dx[d]);
                    ds = fmaf(dx[d], sg[j * 6 + d], ds);
                }
                red[6] = -2.0f * gamma * kap * ds;
                red[7] = 2.0f * gamma * dsq * kap - 6.0f * kap;
#pragma unroll
                for (int q = 0; q < 8; q++)
#pragma unroll
                    for (int off = 16; off > 0; off >>= 1)
                        red[q] += __shfl_xor_sync(0xFFFFFFFFu, red[q], off);
                if (lane == 0) {
#pragma unroll
                    for (int d = 0; d < 6; d++) {
                        float xn = Xg[i * 6 + d] + LRATE * (red[d] * (1.0f / 32.0f));
                        Xn[i * 6 + d] = fminf(fmaxf(xn, -CLIP_LIM), CLIP_LIM);
                    }
                    const float l4 = red[6] * (1.0f / 32.0f);
                    const float l5 = -2.0f * gamma * (red[7] * (1.0f / 32.0f));
                    sm->logp[g * 32 + i] -= LRATE * (l4 + l5);
                }
            }
        }
        cur ^= 1;
        __syncthreads();
    }

    // ---- outputs ----------------------------------------------------------
    for (int i = tid; i < 768; i += 512) g_out[bx * 768 + i] = sm->X[cur][i];
    if (tid < 128) g_out[BATCH * NP * DD + bx * 128 + tid] = sm->logp[tid];
}

// ---------------------------------------------------------------------------
extern "C" void kernel_launch(void* const* d_in, const int* in_sizes, int n_in,
                              void* d_out, int out_size) {
    const float* obs = (const float*)d_in[0];
    const float* a   = (const float*)d_in[1];
    const float* W1  = (const float*)d_in[2];
    const float* b1  = (const float*)d_in[3];
    const float* W2  = (const float*)d_in[4];
    const float* b2  = (const float*)d_in[5];
    const float* W3  = (const float*)d_in[6];
    // d_in[7] = b3: unused (does not affect gradients/outputs)
    float* out = (float*)d_out;

    prep_kernel<<<128, 256>>>(W1, W2, W3);
    cudaFuncSetAttribute(svgd_kernel, cudaFuncAttributeMaxDynamicSharedMemorySize,
                         (int)sizeof(SM));
    svgd_kernel<<<512, 512, sizeof(SM)>>>(obs, a, b1, b2, out);
}

// round 10
// speedup vs baseline: 2.1487x; 1.2049x over previous
#include <cuda_runtime.h>
#include <cuda_bf16.h>
#include <stdint.h>
#include <math.h>

#define BATCH 2048
#define NP 32
#define DD 6
#define NOBS 17
#define HID 256
#define NSTEPS 10
#define LRATE 0.1f
#define CLIP_LIM 1.0f
#define LOG_NP1 3.49650756f

// ---- pre-baked B-operand images (bf16 hi/lo pairs packed in u32) ----------
// Layout: chunk c holds k in [32c,32c+32); within chunk: row n (0..255) of 16
// u32 units (unit = bf16 pair (k,k+1)); unit index swizzled:
//   idx = c*4096 + n*16 + (kp ^ (((n>>1)&3)<<2)),  kp = (k%32)/2
__device__ unsigned g_BfH[32768], g_BfL[32768];   // fwd  B[n][k] = W2[k][n]
__device__ unsigned g_BbH[32768], g_BbL[32768];   // bwd  B[n][k] = W2[n][k]
__device__ unsigned g_W1H[4096],  g_W1L[4096];    // z1   B[n][k] = W1[k][n], K=32 pad
__device__ float g_W1xT[HID * DD];
__device__ unsigned short g_W3H[HID], g_W3L[HID];

__device__ __forceinline__ void split2(float v0, float v1, unsigned& hi, unsigned& lo) {
    __nv_bfloat16 h0 = __float2bfloat16(v0), h1 = __float2bfloat16(v1);
    float r0 = v0 - __bfloat162float(h0), r1 = v1 - __bfloat162float(h1);
    hi = (unsigned)__bfloat16_as_ushort(h0) | ((unsigned)__bfloat16_as_ushort(h1) << 16);
    lo = (unsigned)__bfloat16_as_ushort(__float2bfloat16(r0)) |
         ((unsigned)__bfloat16_as_ushort(__float2bfloat16(r1)) << 16);
}

__device__ __forceinline__ unsigned su32(const void* p) {
    unsigned a;
    asm("{ .reg .u64 t; cvta.to.shared.u64 t, %1; cvt.u32.u64 %0, t; }" : "=r"(a) : "l"(p));
    return a;
}
#define CPA16(d, s) asm volatile("cp.async.cg.shared.global [%0], [%1], 16;" :: "r"(d), "l"(s))
#define CPC()       asm volatile("cp.async.commit_group;" ::: "memory")
#define CPW0()      asm volatile("cp.async.wait_group 0;" ::: "memory")

__device__ __forceinline__ void mma16816(float* c, const unsigned* a, unsigned b0, unsigned b1) {
    asm volatile(
        "mma.sync.aligned.m16n8k16.row.col.f32.bf16.bf16.f32 "
        "{%0,%1,%2,%3}, {%4,%5,%6,%7}, {%8,%9}, {%0,%1,%2,%3};"
        : "+f"(c[0]), "+f"(c[1]), "+f"(c[2]), "+f"(c[3])
        : "r"(a[0]), "r"(a[1]), "r"(a[2]), "r"(a[3]), "r"(b0), "r"(b1));
}

// ---- prep: bake weight images --------------------------------------------
__global__ void prep_kernel(const float* __restrict__ W1, const float* __restrict__ W2,
                            const float* __restrict__ W3) {
    const int t = blockIdx.x * 256 + threadIdx.x;   // 128 blocks x 256
    const int n = t >> 7, kp = t & 127, k = kp * 2;
    const int idx = (kp >> 4) * 4096 + n * 16 + ((kp & 15) ^ (((n >> 1) & 3) << 2));
    unsigned hi, lo;
    split2(W2[k * 256 + n], W2[(k + 1) * 256 + n], hi, lo);   // fwd
    g_BfH[idx] = hi; g_BfL[idx] = lo;
    split2(W2[n * 256 + k], W2[n * 256 + k + 1], hi, lo);     // bwd
    g_BbH[idx] = hi; g_BbL[idx] = lo;
    if (kp < 16) {
        float v0 = (k < 23) ? W1[k * 256 + n] : 0.0f;
        float v1 = (k + 1 < 23) ? W1[(k + 1) * 256 + n] : 0.0f;
        split2(v0, v1, hi, lo);
        const int i2 = n * 16 + (kp ^ (((n >> 1) & 3) << 2));
        g_W1H[i2] = hi; g_W1L[i2] = lo;
    }
    if (kp < 6) g_W1xT[n * 6 + kp] = W1[(17 + kp) * 256 + n];
    if (kp == 0) {
        __nv_bfloat16 h = __float2bfloat16(W3[n]);
        g_W3H[n] = __bfloat16_as_ushort(h);
        g_W3L[n] = __bfloat16_as_ushort(__float2bfloat16(W3[n] - __bfloat162float(h)));
    }
}

// ---- shared memory --------------------------------------------------------
// A images: [m 0..127][unit kp 0..127], idx = m*128 + (kp ^ ((m&7)<<2))
struct __align__(16) SM {
    unsigned Ah[16384], Al[16384];          // 64KB + 64KB
    unsigned Bh[2][4096], Bl[2][4096];      // double-buffered 16KB chunks
    float X[2][128 * 6];
    float s[128 * 6];
    float scratch[128 * 6 * 4];             // spart
    float W1xT[256 * 6];
    float b1[256], b2[256];
    float logp[128];
    float gamma[4];
    unsigned short W3H[256], W3L[256];
};

extern __shared__ char smraw[];

__device__ __forceinline__ void issue_chunk(SM* sm, int buf,
                                            const unsigned* __restrict__ gBh,
                                            const unsigned* __restrict__ gBl,
                                            int ch, int tid) {
    const unsigned dH = su32(sm->Bh[buf]), dL = su32(sm->Bl[buf]);
    const char* sH = (const char*)(gBh + ch * 4096);
    const char* sL = (const char*)(gBl + ch * 4096);
    for (int i = tid; i < 1024; i += 512) {
        CPA16(dH + i * 16, sH + i * 16);
        CPA16(dL + i * 16, sL + i * 16);
    }
    CPC();
}

// Double-buffered GEMM: M=128, N=256, K = 32*NCHUNK, bf16x3.
// Single barrier per chunk: wait(ch) -> bar -> issue(ch+1) -> compute(ch).
// Buffer reuse is safe: readers of buf[(ch+1)&1] (chunk ch-1) passed this
// iteration's barrier before the new issue starts writing it.
template <int NCHUNK>
__device__ __forceinline__ void gemm_mma(SM* sm, const unsigned* __restrict__ gBh,
                                         const unsigned* __restrict__ gBl,
                                         float acc[2][8][4], int m0, int n0,
                                         int lane, int tid) {
#pragma unroll
    for (int i = 0; i < 2; i++)
#pragma unroll
        for (int j = 0; j < 8; j++)
#pragma unroll
            for (int e = 0; e < 4; e++) acc[i][j][e] = 0.0f;
    const int swA = (lane >> 2) << 2;

    issue_chunk(sm, 0, gBh, gBl, 0, tid);
    for (int ch = 0; ch < NCHUNK; ch++) {
        CPW0();                     // chunk ch landed (own copies)
        __syncthreads();            // all copies visible; prior readers done
        if (ch + 1 < NCHUNK) issue_chunk(sm, (ch + 1) & 1, gBh, gBl, ch + 1, tid);
        const unsigned* Bhc = sm->Bh[ch & 1];
        const unsigned* Blc = sm->Bl[ch & 1];
#pragma unroll
        for (int pass = 0; pass < 3; pass++) {
            const unsigned* A = (pass == 2) ? sm->Al : sm->Ah;
            const unsigned* B = (pass == 1) ? Blc : Bhc;
#pragma unroll
            for (int ks = 0; ks < 2; ks++) {
                const int kpb = ch * 16 + ks * 8 + (lane & 3);
                const int kpl = ks * 8 + (lane & 3);
                unsigned af[2][4];
#pragma unroll
                for (int mt = 0; mt < 2; mt++) {
                    const int r = m0 + mt * 16 + (lane >> 2);
                    af[mt][0] = A[r * 128 + (kpb ^ swA)];
                    af[mt][1] = A[(r + 8) * 128 + (kpb ^ swA)];
                    af[mt][2] = A[r * 128 + ((kpb + 4) ^ swA)];
                    af[mt][3] = A[(r + 8) * 128 + ((kpb + 4) ^ swA)];
                }
#pragma unroll
                for (int nt = 0; nt < 8; nt++) {
                    const int n = n0 + nt * 8 + (lane >> 2);
                    const int swb = ((n >> 1) & 3) << 2;
                    const unsigned b0 = B[n * 16 + (kpl ^ swb)];
                    const unsigned b1 = B[n * 16 + ((kpl + 4) ^ swb)];
                    mma16816(acc[0][nt], af[0], b0, b1);
                    mma16816(acc[1][nt], af[1], b0, b1);
                }
            }
        }
    }
    __syncthreads();                // A-image readers done before epilogue writes
}

__global__ void __launch_bounds__(512, 1) svgd_kernel(
    const float* __restrict__ g_obs, const float* __restrict__ g_a,
    const float* __restrict__ g_b1, const float* __restrict__ g_b2,
    float* __restrict__ g_out)
{
    SM* sm = (SM*)smraw;
    const int tid = threadIdx.x, bx = blockIdx.x;
    const int warp = tid >> 5, lane = tid & 31;
    const int m0 = (warp & 3) * 32;          // warp row tile
    const int wN = warp >> 2;                // warp col group
    const int n0 = wN * 64;
    const int swA = (lane >> 2) << 2;

    // ---- prologue ---------------------------------------------------------
    if (tid < 256) {
        sm->b1[tid] = g_b1[tid];
        sm->b2[tid] = g_b2[tid];
        sm->W3H[tid] = g_W3H[tid];
        sm->W3L[tid] = g_W3L[tid];
    }
    for (int i = tid; i < 1536; i += 512) sm->W1xT[i] = g_W1xT[i];
    for (int i = tid; i < 768; i += 512) sm->X[0][i] = g_a[bx * 768 + i];
    if (tid < 128) sm->logp[tid] = 0.0f;
    __syncthreads();

    int cur = 0;
    float acc[2][8][4];
    unsigned mk[2];

    for (int step = 0; step < NSTEPS; step++) {
        // ---- build z1 A image: obs + X + pad (kp 0..15) -----------------
        for (int idx = tid; idx < 128 * 16; idx += 512) {
            const int row = idx >> 4, kp = idx & 15, k0 = kp * 2;
            float v0, v1;
            v0 = (k0 < NOBS) ? g_obs[(bx * 128 + row) * NOBS + k0]
               : (k0 < 23)   ? sm->X[cur][row * 6 + k0 - NOBS] : 0.0f;
            const int k1 = k0 + 1;
            v1 = (k1 < NOBS) ? g_obs[(bx * 128 + row) * NOBS + k1]
               : (k1 < 23)   ? sm->X[cur][row * 6 + k1 - NOBS] : 0.0f;
            unsigned hi, lo;
            split2(v0, v1, hi, lo);
            const int o = row * 128 + (kp ^ ((row & 7) << 2));
            sm->Ah[o] = hi; sm->Al[o] = lo;
        }
        // (gemm's first barrier orders these writes before MMA reads)

        // ---- z1 GEMM + epilogue: h1 = relu(z1+b1), mask, split ----------
        gemm_mma<1>(sm, g_W1H, g_W1L, acc, m0, n0, lane, tid);
        mk[0] = 0u; mk[1] = 0u;
#pragma unroll
        for (int mt = 0; mt < 2; mt++) {
            const int rA = m0 + mt * 16 + (lane >> 2);
#pragma unroll
            for (int nt = 0; nt < 8; nt++) {
                const int cA = n0 + nt * 8 + ((lane & 3) << 1);
                const int kp = cA >> 1;
                float h0 = fmaxf(acc[mt][nt][0] + sm->b1[cA], 0.0f);
                float h1 = fmaxf(acc[mt][nt][1] + sm->b1[cA + 1], 0.0f);
                float h2 = fmaxf(acc[mt][nt][2] + sm->b1[cA], 0.0f);
                float h3 = fmaxf(acc[mt][nt][3] + sm->b1[cA + 1], 0.0f);
                if (h0 > 0.0f) mk[mt] |= 1u << (nt * 4 + 0);
                if (h1 > 0.0f) mk[mt] |= 1u << (nt * 4 + 1);
                if (h2 > 0.0f) mk[mt] |= 1u << (nt * 4 + 2);
                if (h3 > 0.0f) mk[mt] |= 1u << (nt * 4 + 3);
                unsigned hi, lo;
                split2(h0, h1, hi, lo);
                int o = rA * 128 + (kp ^ swA);
                sm->Ah[o] = hi; sm->Al[o] = lo;
                split2(h2, h3, hi, lo);
                o = (rA + 8) * 128 + (kp ^ swA);
                sm->Ah[o] = hi; sm->Al[o] = lo;
            }
        }

        // ---- fwd GEMM (z2) + epilogue: dz2 = (z2+b2>0)*W3 ---------------
        gemm_mma<8>(sm, g_BfH, g_BfL, acc, m0, n0, lane, tid);
#pragma unroll
        for (int mt = 0; mt < 2; mt++) {
            const int rA = m0 + mt * 16 + (lane >> 2);
#pragma unroll
            for (int nt = 0; nt < 8; nt++) {
                const int cA = n0 + nt * 8 + ((lane & 3) << 1);
                const int kp = cA >> 1;
                const bool s0 = acc[mt][nt][0] + sm->b2[cA] > 0.0f;
                const bool s1 = acc[mt][nt][1] + sm->b2[cA + 1] > 0.0f;
                const bool s2 = acc[mt][nt][2] + sm->b2[cA] > 0.0f;
                const bool s3 = acc[mt][nt][3] + sm->b2[cA + 1] > 0.0f;
                const unsigned h0 = s0 ? sm->W3H[cA] : 0, h1 = s1 ? sm->W3H[cA + 1] : 0;
                const unsigned h2 = s2 ? sm->W3H[cA] : 0, h3 = s3 ? sm->W3H[cA + 1] : 0;
                const unsigned l0 = s0 ? sm->W3L[cA] : 0, l1 = s1 ? sm->W3L[cA + 1] : 0;
                const unsigned l2 = s2 ? sm->W3L[cA] : 0, l3 = s3 ? sm->W3L[cA + 1] : 0;
                int o = rA * 128 + (kp ^ swA);
                sm->Ah[o] = h0 | (h1 << 16); sm->Al[o] = l0 | (l1 << 16);
                o = (rA + 8) * 128 + (kp ^ swA);
                sm->Ah[o] = h2 | (h3 << 16); sm->Al[o] = l2 | (l3 << 16);
            }
        }

        // ---- bwd GEMM (dz1) + epilogue: mask + fold score matmul --------
        gemm_mma<8>(sm, g_BbH, g_BbL, acc, m0, n0, lane, tid);
        {
            float sp[4][6];
#pragma unroll
            for (int s = 0; s < 4; s++)
#pragma unroll
                for (int d = 0; d < 6; d++) sp[s][d] = 0.0f;
#pragma unroll
            for (int mt = 0; mt < 2; mt++)
#pragma unroll
                for (int nt = 0; nt < 8; nt++)
#pragma unroll
                    for (int e = 0; e < 4; e++) {
                        const float v = ((mk[mt] >> (nt * 4 + e)) & 1u)
                                            ? acc[mt][nt][e] : 0.0f;
                        const int c = n0 + nt * 8 + ((lane & 3) << 1) + (e & 1);
                        const int s = mt * 2 + (e >> 1);
                        const float* w = &sm->W1xT[c * 6];
#pragma unroll
                        for (int d = 0; d < 6; d++) sp[s][d] = fmaf(v, w[d], sp[s][d]);
                    }
#pragma unroll
            for (int s = 0; s < 4; s++)
#pragma unroll
                for (int d = 0; d < 6; d++) {
                    sp[s][d] += __shfl_xor_sync(0xFFFFFFFFu, sp[s][d], 1);
                    sp[s][d] += __shfl_xor_sync(0xFFFFFFFFu, sp[s][d], 2);
                }
            if ((lane & 3) == 0) {
#pragma unroll
                for (int s = 0; s < 4; s++) {
                    const int row = m0 + (s >> 1) * 16 + (s & 1) * 8 + (lane >> 2);
#pragma unroll
                    for (int d = 0; d < 6; d++)
                        sm->scratch[(row * 6 + d) * 4 + wN] = sp[s][d];
                }
            }
        }
        __syncthreads();
        for (int i = tid; i < 768; i += 512)
            sm->s[i] = sm->scratch[4 * i] + sm->scratch[4 * i + 1] +
                       sm->scratch[4 * i + 2] + sm->scratch[4 * i + 3];

        // ---- median: warp-local register bitonic sort (warps 0-3) -------
        // 512 elems = 496 upper-tri dists + inf pad; elem e = r*32 + lane.
        // Multiset median idx 511 of 1024 -> sorted-pairs idx 239 = (r7,l15).
        if (warp < 4) {
            const int g = warp;
            const float* Xg = &sm->X[cur][g * 192];
            float v[16];
#pragma unroll
            for (int r = 0; r < 16; r++) {
                const int e = r * 32 + lane;
                float val = __int_as_float(0x7f800000);
                if (e < 496) {
                    // triangular index -> (i,j): off(i) = i*(63-i)/2
                    int i = (int)((63.0f - sqrtf(3969.0f - 8.0f * (float)e)) * 0.5f);
                    int off = (i * (63 - i)) >> 1;
                    if (e < off) { i--; off = (i * (63 - i)) >> 1; }
                    else {
                        const int off2 = ((i + 1) * (62 - i)) >> 1;
                        if (e >= off2) { i++; off = off2; }
                    }
                    const int j = i + 1 + (e - off);
                    float ds = 0.0f;
#pragma unroll
                    for (int d = 0; d < 6; d++) {
                        const float dx = Xg[i * 6 + d] - Xg[j * 6 + d];
                        ds = fmaf(dx, dx, ds);
                    }
                    val = ds;
                }
                v[r] = val;
            }
#pragma unroll
            for (int k = 2; k <= 512; k <<= 1) {
#pragma unroll
                for (int j = k >> 1; j > 0; j >>= 1) {
                    if (j >= 32) {
                        const int rr = j >> 5;
#pragma unroll
                        for (int r = 0; r < 16; r++)
                            if (!(r & rr)) {
                                const int rp = r | rr;
                                const bool asc = ((r & (k >> 5)) == 0);
                                const float a = v[r], b = v[rp];
                                const float mn = fminf(a, b), mx = fmaxf(a, b);
                                v[r]  = asc ? mn : mx;
                                v[rp] = asc ? mx : mn;
                            }
                    } else {
#pragma unroll
                        for (int r = 0; r < 16; r++) {
                            const bool asc = (k >= 32) ? ((r & (k >> 5)) == 0)
                                                       : ((lane & k) == 0);
                            const float pv = __shfl_xor_sync(0xFFFFFFFFu, v[r], j);
                            const bool lower = ((lane & j) == 0);
                            const float mn = fminf(v[r], pv), mx = fmaxf(v[r], pv);
                            v[r] = (lower == asc) ? mn : mx;
                        }
                    }
                }
            }
            if (lane == 15) {
                const float hm = v[7] / (2.0f * LOG_NP1);
                sm->gamma[g] = 1.0f / (1e-8f + 2.0f * hm);
            }
        }
        __syncthreads();

        // ---- RBF phi / logp (4 warps per batch, 8 rows per warp) --------
        {
            const int g = warp >> 2, rb = (warp & 3) * 8;
            const float gamma = sm->gamma[g];
            const float* Xg = &sm->X[cur][g * 192];
            float* Xn = &sm->X[cur ^ 1][g * 192];
            const float* sg = &sm->s[g * 192];
            for (int ii = 0; ii < 8; ii++) {
                const int i = rb + ii, j = lane;
                float dx[6], red[8], ds = 0.0f, dsq = 0.0f;
#pragma unroll
                for (int d = 0; d < 6; d++) {
                    dx[d] = Xg[i * 6 + d] - Xg[j * 6 + d];
                    dsq = fmaf(dx[d], dx[d], dsq);
                }
                const float kap = __expf(-gamma * dsq);
#pragma unroll
                for (int d = 0; d < 6; d++) {
                    red[d] = kap * (sg[j * 6 + d] + 2.0f * gamma * dx[d]);
                    ds = fmaf(dx[d], sg[j * 6 + d], ds);
                }
                red[6] = -2.0f * gamma * kap * ds;
                red[7] = 2.0f * gamma * dsq * kap - 6.0f * kap;
#pragma unroll
                for (int q = 0; q < 8; q++)
#pragma unroll
                    for (int off = 16; off > 0; off >>= 1)
                        red[q] += __shfl_xor_sync(0xFFFFFFFFu, red[q], off);
                if (lane == 0) {
#pragma unroll
                    for (int d = 0; d < 6; d++) {
                        float xn = Xg[i * 6 + d] + LRATE * (red[d] * (1.0f / 32.0f));
                        Xn[i * 6 + d] = fminf(fmaxf(xn, -CLIP_LIM), CLIP_LIM);
                    }
                    const float l4 = red[6] * (1.0f / 32.0f);
                    const float l5 = -2.0f * gamma * (red[7] * (1.0f / 32.0f));
                    sm->logp[g * 32 + i] -= LRATE * (l4 + l5);
                }
            }
        }
        cur ^= 1;
        __syncthreads();
    }

    // ---- outputs ----------------------------------------------------------
    for (int i = tid; i < 768; i += 512) g_out[bx * 768 + i] = sm->X[cur][i];
    if (tid < 128) g_out[BATCH * NP * DD + bx * 128 + tid] = sm->logp[tid];
}

// ---------------------------------------------------------------------------
extern "C" void kernel_launch(void* const* d_in, const int* in_sizes, int n_in,
                              void* d_out, int out_size) {
    const float* obs = (const float*)d_in[0];
    const float* a   = (const float*)d_in[1];
    const float* W1  = (const float*)d_in[2];
    const float* b1  = (const float*)d_in[3];
    const float* W2  = (const float*)d_in[4];
    const float* b2  = (const float*)d_in[5];
    const float* W3  = (const float*)d_in[6];
    // d_in[7] = b3: unused (does not affect gradients/outputs)
    float* out = (float*)d_out;

    prep_kernel<<<128, 256>>>(W1, W2, W3);
    cudaFuncSetAttribute(svgd_kernel, cudaFuncAttributeMaxDynamicSharedMemorySize,
                         (int)sizeof(SM));
    svgd_kernel<<<512, 512, sizeof(SM)>>>(obs, a, b1, b2, out);
}